// round 11
// baseline (speedup 1.0000x reference)
#include <cuda_runtime.h>
#include <cuda_bf16.h>
#include <math.h>
#include <stdint.h>

// Problem constants
#define Bn   4
#define Tn   4096
#define Dn   1024
#define Hn   16
#define HD   64
#define BH   64            // Bn*Hn
#define NCH  32            // Tn/128
#define Mn   16384         // Bn*Tn

// tcgen05 only on arch-specific passes; plain compute_103 pass compiles a stub
// (never executed — driver picks the sm_103a cubin; guards cover it anyway).
#if defined(__CUDA_ARCH_FEAT_SM103_ALL) || defined(__CUDA_ARCH_FEAT_SM100_ALL) || \
    defined(__CUDA_ARCH_FEAT_SM101_ALL) || defined(__CUDA_ARCH_FEAT_SM110_ALL) || \
    (defined(__CUDA_ARCH_FAMILY_SPECIFIC__) && (__CUDA_ARCH_FAMILY_SPECIFIC__ >= 1000))
#define HAS_TC 1
#else
#define HAS_TC 0
#endif

// Scratch (device globals; no allocations allowed)
static __device__ float    g_q[(size_t)BH * Tn * HD];
static __device__ float    g_k[(size_t)BH * Tn * HD];
static __device__ float    g_v[(size_t)BH * Tn * HD];
static __device__ float    g_xo[(size_t)Mn * Dn];
static __device__ unsigned g_keys[BH * Tn];
static __device__ int      g_sidx[BH * Tn];
static __device__ int      g_flags[2];

// bf16 hi/lo operand buffers (pre-converted off the GEMM critical path)
static __device__ __nv_bfloat16 g_xh[(size_t)Mn * Dn];
static __device__ __nv_bfloat16 g_xl[(size_t)Mn * Dn];
static __device__ __nv_bfloat16 g_xoh[(size_t)Mn * Dn];
static __device__ __nv_bfloat16 g_xol[(size_t)Mn * Dn];
static __device__ __nv_bfloat16 g_wkvh[(size_t)2048 * Dn];  // W_attn cols 1024..3071, [n][k]
static __device__ __nv_bfloat16 g_wkvl[(size_t)2048 * Dn];
static __device__ __nv_bfloat16 g_wph[(size_t)Dn * Dn];     // W_proj transposed [n][k]
static __device__ __nv_bfloat16 g_wpl[(size_t)Dn * Dn];

// ---------------------------------------------------------------------------
#define SMEM_SWIZZLE_128B(bo) ((bo) ^ (((bo) >> 3) & 0x70))

__device__ __forceinline__ void split_bf16(float v, uint16_t& hi, uint16_t& lo) {
    uint16_t h = __bfloat16_as_ushort(__float2bfloat16(v));
    float hf = __uint_as_float((uint32_t)h << 16);
    lo = __bfloat16_as_ushort(__float2bfloat16(v - hf));
    hi = h;
}

#if HAS_TC
__device__ __forceinline__ uint32_t elect_one_pred() {
    uint32_t pred;
    asm volatile("{\n\t.reg .pred p;\n\telect.sync _|p, 0xFFFFFFFF;\n\t"
                 "selp.b32 %0, 1, 0, p;\n\t}" : "=r"(pred));
    return pred;
}
__device__ __forceinline__ uint32_t smem_to_u32(const void* p) {
    uint32_t a;
    asm("{ .reg .u64 t; cvta.to.shared.u64 t, %1; cvt.u32.u64 %0, t; }"
        : "=r"(a) : "l"(p));
    return a;
}

static constexpr uint64_t SMEM_DESC_BASE_SW128 =
    (uint64_t(2)  << 61) | (uint64_t(1) << 46) | (uint64_t(64) << 32) | (uint64_t(1) << 16);
#define MAKE_SMEM_DESC(base_addr) \
    (SMEM_DESC_BASE_SW128 | ((uint64_t)((base_addr) >> 4) & 0x3FFF))

#define TCGEN05_ALLOC(smem_result_addr, nCols) \
    asm volatile("tcgen05.alloc.cta_group::1.sync.aligned.shared::cta.b32 [%0], %1;" \
        :: "r"((uint32_t)(smem_result_addr)), "r"((uint32_t)(nCols)) : "memory")
#define TCGEN05_DEALLOC(tmem_addr, nCols) \
    asm volatile("tcgen05.dealloc.cta_group::1.sync.aligned.b32 %0, %1;" \
        :: "r"(tmem_addr), "r"((uint32_t)(nCols)))
#define TCGEN05_COMMIT(mbar) \
    asm volatile("tcgen05.commit.cta_group::1.mbarrier::arrive::one.shared::cluster.b64 [%0];" \
        :: "r"((uint32_t)(mbar)) : "memory")
#define TCGEN05_FENCE_AFTER() \
    asm volatile("tcgen05.fence::after_thread_sync;" ::: "memory")
#define TCGEN05_FENCE_BEFORE() \
    asm volatile("tcgen05.fence::before_thread_sync;" ::: "memory")
#define TCGEN05_WAIT_LD() \
    asm volatile("tcgen05.wait::ld.sync.aligned;" ::: "memory")
#define TCGEN05_WAIT_ST() \
    asm volatile("tcgen05.wait::st.sync.aligned;" ::: "memory")

#define MBARRIER_INIT(mbar, count) \
    asm volatile("mbarrier.init.shared.b64 [%0], %1;" \
        :: "r"((uint32_t)(mbar)), "r"((uint32_t)(count)) : "memory")
#define MBARRIER_WAIT_PARITY(mbar_smem_addr, phase_parity) do { \
    uint32_t _mbar = (uint32_t)(mbar_smem_addr); \
    uint32_t _parity = (uint32_t)(phase_parity); \
    uint32_t _done; \
    asm volatile("{\n\t.reg .pred p;\n\t" \
        "mbarrier.try_wait.parity.acquire.cta.shared::cta.b64 p, [%1], %2;\n\t" \
        "selp.b32 %0, 1, 0, p;\n\t}" \
        : "=r"(_done) : "r"(_mbar), "r"(_parity) : "memory"); \
    if (!_done) { \
        asm volatile("{\n\t.reg .pred P1;\n\t" \
            "WAIT_LOOP_%=:\n\t" \
            "mbarrier.try_wait.parity.acquire.cta.shared::cta.b64 P1, [%0], %1, 0x989680;\n\t" \
            "@P1 bra.uni WAIT_DONE_%=;\n\t" \
            "bra.uni WAIT_LOOP_%=;\n\t" \
            "WAIT_DONE_%=:\n\t}" \
            :: "r"(_mbar), "r"(_parity) : "memory"); \
    } \
} while(0)

#define TCGEN05_LD_32X32B_X32(r, tmem_addr) \
    asm volatile("tcgen05.ld.sync.aligned.32x32b.x32.b32 " \
        "{%0, %1, %2, %3, %4, %5, %6, %7, %8, %9, %10, %11, %12, %13, %14, %15, " \
        " %16, %17, %18, %19, %20, %21, %22, %23, %24, %25, %26, %27, %28, %29, %30, %31}, [%32];" \
        : "=r"((r)[0]),  "=r"((r)[1]),  "=r"((r)[2]),  "=r"((r)[3]), \
          "=r"((r)[4]),  "=r"((r)[5]),  "=r"((r)[6]),  "=r"((r)[7]), \
          "=r"((r)[8]),  "=r"((r)[9]),  "=r"((r)[10]), "=r"((r)[11]), \
          "=r"((r)[12]), "=r"((r)[13]), "=r"((r)[14]), "=r"((r)[15]), \
          "=r"((r)[16]), "=r"((r)[17]), "=r"((r)[18]), "=r"((r)[19]), \
          "=r"((r)[20]), "=r"((r)[21]), "=r"((r)[22]), "=r"((r)[23]), \
          "=r"((r)[24]), "=r"((r)[25]), "=r"((r)[26]), "=r"((r)[27]), \
          "=r"((r)[28]), "=r"((r)[29]), "=r"((r)[30]), "=r"((r)[31]) \
        : "r"(tmem_addr))

#define TCGEN05_ST_32X32B_X32(tmem_addr, r) \
    asm volatile("tcgen05.st.sync.aligned.32x32b.x32.b32 [%0], " \
        "{%1, %2, %3, %4, %5, %6, %7, %8, %9, %10, %11, %12, %13, %14, %15, %16, " \
        " %17, %18, %19, %20, %21, %22, %23, %24, %25, %26, %27, %28, %29, %30, %31, %32};" \
        :: "r"(tmem_addr), \
           "r"((r)[0]),  "r"((r)[1]),  "r"((r)[2]),  "r"((r)[3]), \
           "r"((r)[4]),  "r"((r)[5]),  "r"((r)[6]),  "r"((r)[7]), \
           "r"((r)[8]),  "r"((r)[9]),  "r"((r)[10]), "r"((r)[11]), \
           "r"((r)[12]), "r"((r)[13]), "r"((r)[14]), "r"((r)[15]), \
           "r"((r)[16]), "r"((r)[17]), "r"((r)[18]), "r"((r)[19]), \
           "r"((r)[20]), "r"((r)[21]), "r"((r)[22]), "r"((r)[23]), \
           "r"((r)[24]), "r"((r)[25]), "r"((r)[26]), "r"((r)[27]), \
           "r"((r)[28]), "r"((r)[29]), "r"((r)[30]), "r"((r)[31]) \
        : "memory")

// TS-form bf16 MMA — verified working (R7).
#define TCGEN05_MMA_F16_TS(d_tmem, a_tmem, b_desc, idesc, enable_d) do { \
    uint32_t _enable = (enable_d) ? 1 : 0; \
    uint32_t _zero = 0; \
    asm volatile( \
        "{\n\t" \
        ".reg .pred p;\n\t" \
        "setp.ne.u32 p, %6, 0;\n\t" \
        "tcgen05.mma.cta_group::1.kind::f16 [%0], [%1], %2, %3, " \
        "{%4, %4, %4, %4}, p;\n\t" \
        "}" \
        :: "r"(d_tmem), "r"(a_tmem), "l"(b_desc), "r"(idesc), \
           "r"(_zero), "r"(_zero), "r"(_enable) \
        : "memory"); \
} while(0)

#define BF16_IDESC_N32 0x8080490u
#endif  // HAS_TC

// ---------------------------------------------------------------------------
__global__ void clear_flags_kernel() { g_flags[0] = 0; g_flags[1] = 0; }

// ---------------------------------------------------------------------------
// Elementwise fp32 -> bf16 hi/lo split (same layout).
// ---------------------------------------------------------------------------
__global__ __launch_bounds__(256) void conv_split_kernel(
    const float* __restrict__ src, __nv_bfloat16* __restrict__ h,
    __nv_bfloat16* __restrict__ l, int n4)
{
    int idx = blockIdx.x * blockDim.x + threadIdx.x;
    if (idx >= n4) return;
    float4 v = ((const float4*)src)[idx];
    uint16_t h0,l0,h1,l1,h2,l2,h3,l3;
    split_bf16(v.x, h0, l0);
    split_bf16(v.y, h1, l1);
    split_bf16(v.z, h2, l2);
    split_bf16(v.w, h3, l3);
    uint2 vh = make_uint2((uint32_t)h0 | ((uint32_t)h1 << 16),
                          (uint32_t)h2 | ((uint32_t)h3 << 16));
    uint2 vl = make_uint2((uint32_t)l0 | ((uint32_t)l1 << 16),
                          (uint32_t)l2 | ((uint32_t)l3 << 16));
    ((uint2*)h)[idx] = vh;
    ((uint2*)l)[idx] = vl;
}

// ---------------------------------------------------------------------------
// Transpose+split: W[k][Ntot] cols col0..col0+ncols -> Wt_h/l [n][1024] bf16.
// Tiled 32x32 through SMEM; grid (ncols/32, 1024/32), 256 threads.
// ---------------------------------------------------------------------------
__global__ __launch_bounds__(256) void conv_wt_kernel(
    const float* __restrict__ W, int Ntot, int col0,
    __nv_bfloat16* __restrict__ th, __nv_bfloat16* __restrict__ tl)
{
    __shared__ float tile[32][33];
    int tx = threadIdx.x & 31, ty = threadIdx.x >> 5;   // ty 0..7
    int nbase = blockIdx.x * 32, kbase = blockIdx.y * 32;
#pragma unroll
    for (int rr = 0; rr < 32; rr += 8)
        tile[ty + rr][tx] = W[(size_t)(kbase + ty + rr) * Ntot + col0 + nbase + tx];
    __syncthreads();
#pragma unroll
    for (int rr = 0; rr < 32; rr += 8) {
        int n = nbase + ty + rr;
        float v = tile[tx][ty + rr];
        uint16_t h, l;
        split_bf16(v, h, l);
        th[(size_t)n * 1024 + kbase + tx] = __ushort_as_bfloat16(h);
        tl[(size_t)n * 1024 + kbase + tx] = __ushort_as_bfloat16(l);
    }
}

// ---------------------------------------------------------------------------
// tcgen05 GEMM — R7's verified synchronous flow, conversion-free.
// C tile 128x128, K=1024 in 16 chunks of 64. D = Ah*Bh + Ah*Bl + Al*Bh.
// A: bf16 hi/lo [M][1024]; B: bf16 hi/lo TRANSPOSED [n][1024].
// TMEM: alloc 256; D @0..127, Ah @128..159, Al @160..191.
// SMEM: hdr 1KB; Ahs @1024 u32[128][33]; Als @17920; Bh @34816 (4x4KB SW128
//       subtiles); Bl @51200. Total 67584 -> 2 CTAs/SM.
// ---------------------------------------------------------------------------
#define TC_SMEM 67584

__global__ __launch_bounds__(256) void tc_gemm_kernel(
    const __nv_bfloat16* __restrict__ Ah_g, const __nv_bfloat16* __restrict__ Al_g,
    const __nv_bfloat16* __restrict__ Bh_g, const __nv_bfloat16* __restrict__ Bl_g,
    const float* __restrict__ bias, float* __restrict__ C,
    int bn_base, int scatter)
{
    extern __shared__ char smem[];
    int tid = threadIdx.x;
    int bm = blockIdx.y * 128;
    int bn = bn_base + blockIdx.x * 128;
    int nl0 = blockIdx.x * 128;          // local row base into transposed B

#if HAS_TC
    uint32_t sb = smem_to_u32(smem);
    int wid = tid >> 5, lid = tid & 31;

    if (wid == 0) TCGEN05_ALLOC(sb, 256);
    if (tid == 0) MBARRIER_INIT(sb + 16, 1);
    __syncthreads();
    uint32_t tmem;
    asm volatile("ld.shared.b32 %0, [%1];" : "=r"(tmem) : "r"(sb));

    uint32_t* const Ahs = (uint32_t*)(smem + 1024);
    uint32_t* const Als = (uint32_t*)(smem + 17920);
    const uint32_t oBh = 34816, oBl = 51200;
    char* const pBh = smem + oBh;
    char* const pBl = smem + oBl;

    int r_  = tid >> 1;                  // for loads: 2 threads per 128B row
    int c_  = (tid & 1) * 4;             // uint4 index 0..7 split across 2 thr

    for (int c = 0; c < 16; c++) {       // K chunks of 64
        int k0 = c * 64;

        // ---- loads: each tile is 128 rows x 128B (8 uint4). 256 threads:
        //      thread covers row tid>>1, uint4s c_..c_+3 (4 per operand).
        uint4 avh[4], avl[4], bvh[4], bvl[4];
        {
            const uint4* arh = (const uint4*)&Ah_g[(size_t)(bm + r_) * 1024 + k0];
            const uint4* arl = (const uint4*)&Al_g[(size_t)(bm + r_) * 1024 + k0];
            const uint4* brh = (const uint4*)&Bh_g[(size_t)(nl0 + r_) * 1024 + k0];
            const uint4* brl = (const uint4*)&Bl_g[(size_t)(nl0 + r_) * 1024 + k0];
#pragma unroll
            for (int i = 0; i < 4; i++) {
                avh[i] = arh[c_ + i];
                avl[i] = arl[c_ + i];
                bvh[i] = brh[c_ + i];
                bvl[i] = brl[c_ + i];
            }
        }

        // ---- stores: A packed stride-33 (R9-verified), B SW128 subtiles ----
        {
            int nt = r_ >> 5, nr = r_ & 31;
#pragma unroll
            for (int i = 0; i < 4; i++) {
                int cc = c_ + i;                       // uint4 col 0..7
                uint32_t* ah = &Ahs[r_ * 33 + cc * 4];
                uint32_t* al = &Als[r_ * 33 + cc * 4];
                ah[0] = avh[i].x; ah[1] = avh[i].y; ah[2] = avh[i].z; ah[3] = avh[i].w;
                al[0] = avl[i].x; al[1] = avl[i].y; al[2] = avl[i].z; al[3] = avl[i].w;
                uint32_t o2 = nt * 4096 +
                    SMEM_SWIZZLE_128B((uint32_t)(nr * 128 + cc * 16));
                *(uint4*)(pBh + o2) = bvh[i];
                *(uint4*)(pBl + o2) = bvl[i];
            }
        }
        __syncthreads();

        // ---- A -> TMEM (warpgroup 0, one row/thread; verified path) ----
        if (tid < 128) {
            uint32_t hi[32], lo[32];
            const uint32_t* bh = &Ahs[tid * 33];
            const uint32_t* bl = &Als[tid * 33];
#pragma unroll
            for (int j = 0; j < 32; j++) { hi[j] = bh[j]; lo[j] = bl[j]; }
            uint32_t wofs = ((uint32_t)(tid >> 5)) << 21;
            TCGEN05_ST_32X32B_X32(tmem + 128 + wofs, hi);
            TCGEN05_ST_32X32B_X32(tmem + 160 + wofs, lo);
            TCGEN05_WAIT_ST();
        }
        __syncthreads();

        // ---- MMA (warp 0, elected); all threads wait on commit (R7 flow) ----
        if (wid == 0) {
            uint64_t dbh = MAKE_SMEM_DESC(sb + oBh);
            uint64_t dbl = MAKE_SMEM_DESC(sb + oBl);
            if (elect_one_pred()) {
#pragma unroll
                for (int ks = 0; ks < 4; ks++) {
                    uint32_t ah = tmem + 128 + ks * 8;
                    uint32_t al = tmem + 160 + ks * 8;
#pragma unroll
                    for (int nt = 0; nt < 4; nt++) {
                        uint32_t d  = tmem + nt * 32;
                        uint64_t bo = (uint64_t)(nt * 256) + ks * 2;
                        uint32_t en0 = (c > 0 || ks > 0) ? 1u : 0u;
                        TCGEN05_MMA_F16_TS(d, ah, dbh + bo, BF16_IDESC_N32, en0);
                        TCGEN05_MMA_F16_TS(d, ah, dbl + bo, BF16_IDESC_N32, 1u);
                        TCGEN05_MMA_F16_TS(d, al, dbh + bo, BF16_IDESC_N32, 1u);
                    }
                }
                TCGEN05_COMMIT(sb + 16);
            }
        }
        MBARRIER_WAIT_PARITY(sb + 16, c & 1);
        TCGEN05_FENCE_AFTER();
        __syncthreads();
    }

    // Epilogue (R7-verified): warps 0-3 read D in 32-col rounds
    if (wid < 4) {
        int m = bm + wid * 32 + lid;
        int b = m >> 12, t = m & 4095;
#pragma unroll
        for (int g = 0; g < 4; g++) {
            uint32_t r[32];
            TCGEN05_LD_32X32B_X32(r, tmem + g * 32);
            TCGEN05_WAIT_LD();
            int ncol0 = bn + g * 32;
            if (scatter) {
                int which = ncol0 >> 10;               // 1 = k, 2 = v
                float* dst = (which == 1) ? g_k : g_v;
#pragma unroll
                for (int jj = 0; jj < 32; jj += 4) {
                    int n0 = ncol0 + jj;
                    int h = (n0 & 1023) >> 6, j0 = n0 & 63;
                    float* p = dst + (((size_t)(b * Hn + h) * Tn) + t) * HD + j0;
                    float4 v;
                    v.x = __uint_as_float(r[jj + 0]) + bias[n0 + 0];
                    v.y = __uint_as_float(r[jj + 1]) + bias[n0 + 1];
                    v.z = __uint_as_float(r[jj + 2]) + bias[n0 + 2];
                    v.w = __uint_as_float(r[jj + 3]) + bias[n0 + 3];
                    *(float4*)p = v;
                }
            } else {
                float* p = C + (size_t)m * 1024 + ncol0;
#pragma unroll
                for (int jj = 0; jj < 32; jj += 4) {
                    float4 v;
                    v.x = __uint_as_float(r[jj + 0]) + bias[ncol0 + jj + 0];
                    v.y = __uint_as_float(r[jj + 1]) + bias[ncol0 + jj + 1];
                    v.z = __uint_as_float(r[jj + 2]) + bias[ncol0 + jj + 2];
                    v.w = __uint_as_float(r[jj + 3]) + bias[ncol0 + jj + 3];
                    *(float4*)&p[jj] = v;
                }
            }
        }
        TCGEN05_FENCE_BEFORE();
    }
    __syncthreads();
    if (wid == 0) TCGEN05_DEALLOC(tmem, 256);
#else
    // Non-arch-specific compile pass: never executed at runtime (driver loads
    // the sm_103a cubin). If it somehow ran, outputs would be wrong and the
    // check kernels would flag -> guard kernels recompute in FFMA.
    (void)Ah_g; (void)Al_g; (void)Bh_g; (void)Bl_g; (void)bias; (void)C;
#endif
}

// ---------------------------------------------------------------------------
// Check kernels: 1 warp per 128x128 output tile verifies 32 elements.
// ---------------------------------------------------------------------------
__global__ __launch_bounds__(256) void check_kv_kernel(
    const float* __restrict__ x, const float* __restrict__ W,
    const float* __restrict__ bias)
{
    int w = (blockIdx.x * blockDim.x + threadIdx.x) >> 5;
    int lane = threadIdx.x & 31;
    if (w >= 128 * 16) return;
    int ty = w >> 4, tx = w & 15;
    int m  = ty * 128 + ((ty * 7 + tx * 3) & 127);
    int n0 = 1024 + tx * 128 + ((ty * 29 + tx * 13) & 96);
    int n  = n0 + lane;
    float acc = bias[n];
    const float* xr = &x[(size_t)m * 1024];
    for (int k = 0; k < 1024; k++)
        acc += xr[k] * W[(size_t)k * 3072 + n];
    int which = n >> 10;
    const float* dst = (which == 1) ? g_k : g_v;
    int h = (n & 1023) >> 6, j0 = n & 63, b = m >> 12, t = m & 4095;
    float got = dst[(((size_t)(b * Hn + h) * Tn) + t) * HD + j0];
    float diff = fabsf(got - acc);
    if (!(diff <= 3e-3f * (1.0f + fabsf(acc)))) atomicExch(&g_flags[0], 1);
}

__global__ __launch_bounds__(256) void check_proj_kernel(
    const float* __restrict__ W, const float* __restrict__ bias,
    const float* __restrict__ out)
{
    int w = (blockIdx.x * blockDim.x + threadIdx.x) >> 5;
    int lane = threadIdx.x & 31;
    if (w >= 128 * 8) return;
    int ty = w >> 3, tx = w & 7;
    int m  = ty * 128 + ((ty * 7 + tx * 3) & 127);
    int n  = tx * 128 + ((ty * 29 + tx * 13) & 96) + lane;
    float acc = bias[n];
    const float* xr = &g_xo[(size_t)m * 1024];
    for (int k = 0; k < 1024; k++)
        acc += xr[k] * W[(size_t)k * 1024 + n];
    float got = out[(size_t)m * 1024 + n];
    float diff = fabsf(got - acc);
    if (!(diff <= 3e-3f * (1.0f + fabsf(acc)))) atomicExch(&g_flags[1], 1);
}

// ---------------------------------------------------------------------------
// Guarded FFMA GEMMs (run only if the TC result was flagged bad).
// ---------------------------------------------------------------------------
__global__ __launch_bounds__(256) void guard_kv_kernel(
    const float* __restrict__ X, const float* __restrict__ W,
    const float* __restrict__ bias)
{
    if (*(volatile int*)&g_flags[0] == 0) return;
    const int K = Dn, N = 3 * Dn;
    __shared__ float As[8][128];
    __shared__ float Bs[8][128];
    int tid = threadIdx.x;
    int bm = blockIdx.y * 128;
    int bn = 1024 + blockIdx.x * 128;
    int arow = tid >> 1,  acol = (tid & 1) << 2;
    int brow = tid >> 5,  bcol = (tid & 31) << 2;
    const float* Ap = X + (size_t)(bm + arow) * K + acol;
    const float* Bp = W + (size_t)brow * N + bn + bcol;
    int ty = tid >> 4, tx = tid & 15;
    float acc[8][8];
#pragma unroll
    for (int i = 0; i < 8; i++)
#pragma unroll
        for (int j = 0; j < 8; j++) acc[i][j] = 0.f;
    for (int k0 = 0; k0 < K; k0 += 8) {
        float4 a4 = *(const float4*)Ap;
        float4 b4 = *(const float4*)Bp;
        As[acol + 0][arow] = a4.x;
        As[acol + 1][arow] = a4.y;
        As[acol + 2][arow] = a4.z;
        As[acol + 3][arow] = a4.w;
        *(float4*)&Bs[brow][bcol] = b4;
        __syncthreads();
#pragma unroll
        for (int kk = 0; kk < 8; kk++) {
            float a[8], b[8];
            *(float4*)&a[0] = *(const float4*)&As[kk][ty * 8];
            *(float4*)&a[4] = *(const float4*)&As[kk][ty * 8 + 4];
            *(float4*)&b[0] = *(const float4*)&Bs[kk][tx * 8];
            *(float4*)&b[4] = *(const float4*)&Bs[kk][tx * 8 + 4];
#pragma unroll
            for (int i = 0; i < 8; i++)
#pragma unroll
                for (int j = 0; j < 8; j++) acc[i][j] += a[i] * b[j];
        }
        __syncthreads();
        Ap += 8;
        Bp += (size_t)8 * N;
    }
    int n0 = bn + tx * 8;
    int which = n0 >> 10;
    float* dst = (which == 1) ? g_k : g_v;
    int h = (n0 & 1023) >> 6, j0 = n0 & 63;
    float bb[8];
#pragma unroll
    for (int j = 0; j < 8; j++) bb[j] = bias[n0 + j];
#pragma unroll
    for (int i = 0; i < 8; i++) {
        int m = bm + ty * 8 + i;
        int b = m >> 12, t = m & 4095;
        float* row = dst + (((size_t)(b * Hn + h) * Tn) + t) * HD + j0;
#pragma unroll
        for (int j = 0; j < 8; j++) row[j] = acc[i][j] + bb[j];
    }
}

__global__ __launch_bounds__(256) void guard_proj_kernel(
    const float* __restrict__ W, const float* __restrict__ bias,
    float* __restrict__ C)
{
    if (*(volatile int*)&g_flags[1] == 0) return;
    const int K = Dn, N = Dn;
    __shared__ float As[8][128];
    __shared__ float Bs[8][128];
    int tid = threadIdx.x;
    int bm = blockIdx.y * 128;
    int bn = blockIdx.x * 128;
    int arow = tid >> 1,  acol = (tid & 1) << 2;
    int brow = tid >> 5,  bcol = (tid & 31) << 2;
    const float* Ap = g_xo + (size_t)(bm + arow) * K + acol;
    const float* Bp = W + (size_t)brow * N + bn + bcol;
    int ty = tid >> 4, tx = tid & 15;
    float acc[8][8];
#pragma unroll
    for (int i = 0; i < 8; i++)
#pragma unroll
        for (int j = 0; j < 8; j++) acc[i][j] = 0.f;
    for (int k0 = 0; k0 < K; k0 += 8) {
        float4 a4 = *(const float4*)Ap;
        float4 b4 = *(const float4*)Bp;
        As[acol + 0][arow] = a4.x;
        As[acol + 1][arow] = a4.y;
        As[acol + 2][arow] = a4.z;
        As[acol + 3][arow] = a4.w;
        *(float4*)&Bs[brow][bcol] = b4;
        __syncthreads();
#pragma unroll
        for (int kk = 0; kk < 8; kk++) {
            float a[8], b[8];
            *(float4*)&a[0] = *(const float4*)&As[kk][ty * 8];
            *(float4*)&a[4] = *(const float4*)&As[kk][ty * 8 + 4];
            *(float4*)&b[0] = *(const float4*)&Bs[kk][tx * 8];
            *(float4*)&b[4] = *(const float4*)&Bs[kk][tx * 8 + 4];
#pragma unroll
            for (int i = 0; i < 8; i++)
#pragma unroll
                for (int j = 0; j < 8; j++) acc[i][j] += a[i] * b[j];
        }
        __syncthreads();
        Ap += 8;
        Bp += (size_t)8 * N;
    }
    float bb[8];
#pragma unroll
    for (int j = 0; j < 8; j++) bb[j] = bias[bn + tx * 8 + j];
#pragma unroll
    for (int i = 0; i < 8; i++) {
        int m = bm + ty * 8 + i;
        float* row = C + (size_t)m * N + bn + tx * 8;
#pragma unroll
        for (int j = 0; j < 8; j++) row[j] = acc[i][j] + bb[j];
    }
}

// ---------------------------------------------------------------------------
// FFMA GEMM for the Q third (bit-identical to round-0; bucket-stable).
// ---------------------------------------------------------------------------
__global__ __launch_bounds__(256) void gemm_qkv_kernel(
    const float* __restrict__ X, const float* __restrict__ W,
    const float* __restrict__ bias)
{
    const int K = Dn, N = 3 * Dn;
    __shared__ float As[8][128];
    __shared__ float Bs[8][128];
    int tid = threadIdx.x;
    int bm = blockIdx.y * 128;
    int bn = blockIdx.x * 128;
    int arow = tid >> 1,  acol = (tid & 1) << 2;
    int brow = tid >> 5,  bcol = (tid & 31) << 2;
    const float* Ap = X + (size_t)(bm + arow) * K + acol;
    const float* Bp = W + (size_t)brow * N + bn + bcol;
    int ty = tid >> 4, tx = tid & 15;

    float acc[8][8];
#pragma unroll
    for (int i = 0; i < 8; i++)
#pragma unroll
        for (int j = 0; j < 8; j++) acc[i][j] = 0.f;

    for (int k0 = 0; k0 < K; k0 += 8) {
        float4 a4 = *(const float4*)Ap;
        float4 b4 = *(const float4*)Bp;
        As[acol + 0][arow] = a4.x;
        As[acol + 1][arow] = a4.y;
        As[acol + 2][arow] = a4.z;
        As[acol + 3][arow] = a4.w;
        *(float4*)&Bs[brow][bcol] = b4;
        __syncthreads();
#pragma unroll
        for (int kk = 0; kk < 8; kk++) {
            float a[8], b[8];
            *(float4*)&a[0] = *(const float4*)&As[kk][ty * 8];
            *(float4*)&a[4] = *(const float4*)&As[kk][ty * 8 + 4];
            *(float4*)&b[0] = *(const float4*)&Bs[kk][tx * 8];
            *(float4*)&b[4] = *(const float4*)&Bs[kk][tx * 8 + 4];
#pragma unroll
            for (int i = 0; i < 8; i++)
#pragma unroll
                for (int j = 0; j < 8; j++) acc[i][j] += a[i] * b[j];
        }
        __syncthreads();
        Ap += 8;
        Bp += (size_t)8 * N;
    }

    int n0 = bn + tx * 8;
    int h  = (n0 & 1023) >> 6;
    int j0 = n0 & 63;
    float bb[8];
#pragma unroll
    for (int j = 0; j < 8; j++) bb[j] = bias[n0 + j];
#pragma unroll
    for (int i = 0; i < 8; i++) {
        int m = bm + ty * 8 + i;
        int b = m >> 12;
        int t = m & 4095;
        float* row = g_q + (((size_t)(b * Hn + h) * Tn) + t) * HD + j0;
#pragma unroll
        for (int j = 0; j < 8; j++) row[j] = acc[i][j] + bb[j];
    }
}

// ---------------------------------------------------------------------------
__global__ void rope_kernel()
{
    int idx = blockIdx.x * blockDim.x + threadIdx.x;
    if (idx >= BH * Tn * 32) return;
    int p  = idx & 31;
    int rt = idx >> 5;
    int t  = rt & 4095;
    int d0 = p * 2, d1 = p * 2 + 1;
    float e0 = (float)(d0 & 31) * (1.0f / 32.0f);
    float e1 = (float)(d1 & 31) * (1.0f / 32.0f);
    float inv0 = 1.0f / powf(10000.0f, e0);
    float inv1 = 1.0f / powf(10000.0f, e1);
    float a0 = (float)t * inv0, a1 = (float)t * inv1;
    float s0, c0, s1, c1;
    sincosf(a0, &s0, &c0);
    sincosf(a1, &s1, &c1);
    size_t base = (size_t)rt * HD;
    float q0 = g_q[base + d0], q1 = g_q[base + d1];
    g_q[base + d0] = q0 * c0 - q1 * s0;
    g_q[base + d1] = q1 * c1 + q0 * s1;
    float k0 = g_k[base + d0], k1 = g_k[base + d1];
    g_k[base + d0] = k0 * c0 - k1 * s0;
    g_k[base + d1] = k1 * c1 + k0 * s1;
}

// ---------------------------------------------------------------------------
__global__ __launch_bounds__(128) void bucket_kernel(const float* __restrict__ R)
{
    __shared__ float Rs[64 * 32];
    int tid = threadIdx.x;
    for (int i = tid; i < 2048; i += 128) {
        int d = i >> 5, m = i & 31;
        Rs[i] = R[d * 64 + m];
    }
    __syncthreads();

    int idx = blockIdx.x * 128 + tid;
    float q[64];
    const float* qp = &g_q[(size_t)idx * HD];
#pragma unroll
    for (int l = 0; l < 16; l++) *(float4*)&q[l * 4] = *(const float4*)&qp[l * 4];

    float proj[32];
    for (int m = 0; m < 32; m++) {
        float s = 0.f;
#pragma unroll
        for (int d = 0; d < 64; d++) s += q[d] * Rs[d * 32 + m];
        proj[m] = s;
    }
    float best = -1e30f; int bi = 0;
#pragma unroll
    for (int i = 0; i < 64; i++) {
        float v = (i < 32) ? proj[i] : -proj[i - 32];
        if (v > best) { best = v; bi = i; }
    }
    g_keys[idx] = ((unsigned)bi << 12) | (unsigned)(idx & 4095);
}

// ---------------------------------------------------------------------------
__global__ __launch_bounds__(1024) void sort_kernel()
{
    __shared__ unsigned s[4096];
    int bh = blockIdx.x, tid = threadIdx.x;
    for (int i = tid; i < 4096; i += 1024) s[i] = g_keys[bh * 4096 + i];
    __syncthreads();
    for (int k = 2; k <= 4096; k <<= 1) {
        for (int j = k >> 1; j > 0; j >>= 1) {
            for (int i = tid; i < 4096; i += 1024) {
                int ixj = i ^ j;
                if (ixj > i) {
                    unsigned a = s[i], b = s[ixj];
                    bool up = (i & k) == 0;
                    if ((a > b) == up) { s[i] = b; s[ixj] = a; }
                }
            }
            __syncthreads();
        }
    }
    for (int i = tid; i < 4096; i += 1024)
        g_sidx[bh * 4096 + i] = (int)(s[i] & 4095u);
}

// ---------------------------------------------------------------------------
#define ATTN_SMEM ((8192 + 8192 + 128 * 129) * 4)

__global__ __launch_bounds__(128) void attn_kernel()
{
    extern __shared__ float sm[];
    float* Ks = sm;
    float* Vs = sm + 8192;
    float* Ss = sm + 16384;
    __shared__ int sidx_s[128];

    int bc = blockIdx.x;
    int bh = bc >> 5;
    int c  = bc & 31;
    int p0 = c * 128;
    int tid = threadIdx.x;
    const int rowbase = bh * Tn;

    sidx_s[tid] = g_sidx[rowbase + p0 + tid];
    __syncthreads();

    for (int i = tid; i < 128 * 16; i += 128) {
        int r = i >> 4, l = (i & 15) * 4;
        size_t src = ((size_t)(rowbase + sidx_s[r])) * HD + l;
        *(float4*)&Ks[r * 64 + l] = *(const float4*)&g_k[src];
        *(float4*)&Vs[r * 64 + l] = *(const float4*)&g_v[src];
    }
    __syncthreads();

    int r  = tid;
    int si = sidx_s[r];
    float qr[64];
    {
        const float* qp = &g_q[((size_t)(rowbase + si)) * HD];
#pragma unroll
        for (int l = 0; l < 16; l++) *(float4*)&qr[l * 4] = *(const float4*)&qp[l * 4];
    }

    float mx = -1e30f;
    for (int j = 0; j < 128; j++) {
        const float* kp = &Ks[j * 64];
        float s0 = 0.f, s1 = 0.f, s2 = 0.f, s3 = 0.f;
#pragma unroll
        for (int d = 0; d < 64; d += 4) {
            float4 k4 = *(const float4*)&kp[d];
            s0 += qr[d + 0] * k4.x;
            s1 += qr[d + 1] * k4.y;
            s2 += qr[d + 2] * k4.z;
            s3 += qr[d + 3] * k4.w;
        }
        float s = (s0 + s1 + s2 + s3) * 0.125f;
        Ss[r * 129 + j] = s;
        mx = fmaxf(mx, s);
    }

    float sum = 0.f;
#pragma unroll 4
    for (int j = 0; j < 128; j++) {
        float e = __expf(Ss[r * 129 + j] - mx);
        Ss[r * 129 + j] = e;
        sum += e;
    }
    float inv = 1.0f / sum;

    float o[64];
#pragma unroll
    for (int d = 0; d < 64; d++) o[d] = 0.f;
    for (int j = 0; j < 128; j++) {
        float p = Ss[r * 129 + j];
        const float* vp = &Vs[j * 64];
#pragma unroll
        for (int d = 0; d < 64; d += 4) {
            float4 v4 = *(const float4*)&vp[d];
            o[d + 0] += p * v4.x;
            o[d + 1] += p * v4.y;
            o[d + 2] += p * v4.z;
            o[d + 3] += p * v4.w;
        }
    }

    int b = bh >> 4, h = bh & 15;
    float* op = &g_xo[((size_t)(b * Tn + si)) * Dn + h * HD];
#pragma unroll
    for (int l = 0; l < 16; l++) {
        float4 v4 = make_float4(o[l * 4 + 0] * inv, o[l * 4 + 1] * inv,
                                o[l * 4 + 2] * inv, o[l * 4 + 3] * inv);
        *(float4*)&op[l * 4] = v4;
    }
}

// ---------------------------------------------------------------------------
extern "C" void kernel_launch(void* const* d_in, const int* in_sizes, int n_in,
                              void* d_out, int out_size)
{
    const float* x      = (const float*)d_in[0];
    const float* W_attn = (const float*)d_in[1];
    const float* b_attn = (const float*)d_in[2];
    const float* W_proj = (const float*)d_in[3];
    const float* b_proj = (const float*)d_in[4];
    const float* R      = (const float*)d_in[5];
    float* out = (float*)d_out;

    cudaFuncSetAttribute(attn_kernel,
                         cudaFuncAttributeMaxDynamicSharedMemorySize, ATTN_SMEM);
    cudaFuncSetAttribute(tc_gemm_kernel,
                         cudaFuncAttributeMaxDynamicSharedMemorySize, TC_SMEM);

    clear_flags_kernel<<<1, 1>>>();

    // Pre-convert: x -> bf16 hi/lo; W_attn KV panel + W_proj -> transposed hi/lo
    int n4x = Mn * Dn / 4;
    conv_split_kernel<<<(n4x + 255) / 256, 256>>>(x, g_xh, g_xl, n4x);
    dim3 gwk(2048 / 32, 1024 / 32);
    conv_wt_kernel<<<gwk, 256>>>(W_attn, 3 * Dn, 1024, g_wkvh, g_wkvl);
    dim3 gwp(1024 / 32, 1024 / 32);
    conv_wt_kernel<<<gwp, 256>>>(W_proj, Dn, 0, g_wph, g_wpl);

    // Q third: exact fp32 FFMA (bucket-stable)
    dim3 gq(8, Mn / 128);
    gemm_qkv_kernel<<<gq, 256>>>(x, W_attn, b_attn);

    // K,V thirds: conversion-free tcgen05 (R7-verified flow)
    dim3 gkv(16, Mn / 128);
    tc_gemm_kernel<<<gkv, 256, TC_SMEM>>>(g_xh, g_xl, g_wkvh, g_wkvl,
                                          b_attn, g_xo, 1024, 1);
    check_kv_kernel<<<(128 * 16 * 32 + 255) / 256, 256>>>(x, W_attn, b_attn);
    guard_kv_kernel<<<gkv, 256>>>(x, W_attn, b_attn);

    rope_kernel<<<(BH * Tn * 32 + 255) / 256, 256>>>();
    bucket_kernel<<<BH * Tn / 128, 128>>>(R);
    sort_kernel<<<BH, 1024>>>();
    attn_kernel<<<BH * NCH, 128, ATTN_SMEM>>>();

    // Output projection: convert xo, then tcgen05 + verify + fallback
    conv_split_kernel<<<(n4x + 255) / 256, 256>>>(g_xo, g_xoh, g_xol, n4x);
    dim3 go(8, Mn / 128);
    tc_gemm_kernel<<<go, 256, TC_SMEM>>>(g_xoh, g_xol, g_wph, g_wpl,
                                         b_proj, out, 0, 0);
    check_proj_kernel<<<(128 * 8 * 32 + 255) / 256, 256>>>(W_proj, b_proj, out);
    guard_proj_kernel<<<go, 256>>>(W_proj, b_proj, out);
}

// round 12
// speedup vs baseline: 6.0724x; 6.0724x over previous
#include <cuda_runtime.h>
#include <cuda_bf16.h>
#include <math.h>
#include <stdint.h>

// Problem constants
#define Bn   4
#define Tn   4096
#define Dn   1024
#define Hn   16
#define HD   64
#define BH   64            // Bn*Hn
#define NCH  32            // Tn/128
#define Mn   16384         // Bn*Tn

// tcgen05 only on arch-specific passes; plain compute_103 pass gets a stub.
#if defined(__CUDA_ARCH_FEAT_SM103_ALL) || defined(__CUDA_ARCH_FEAT_SM100_ALL) || \
    defined(__CUDA_ARCH_FEAT_SM101_ALL) || defined(__CUDA_ARCH_FEAT_SM110_ALL) || \
    (defined(__CUDA_ARCH_FAMILY_SPECIFIC__) && (__CUDA_ARCH_FAMILY_SPECIFIC__ >= 1000))
#define HAS_TC 1
#else
#define HAS_TC 0
#endif

// Scratch (device globals; no allocations allowed)
static __device__ float    g_q[(size_t)BH * Tn * HD];
static __device__ float    g_k[(size_t)BH * Tn * HD];
static __device__ float    g_v[(size_t)BH * Tn * HD];
static __device__ float    g_xo[(size_t)Mn * Dn];
static __device__ unsigned g_keys[BH * Tn];
static __device__ int      g_sidx[BH * Tn];
static __device__ int      g_flags[2];

// ---------------------------------------------------------------------------
#define SMEM_SWIZZLE_128B(bo) ((bo) ^ (((bo) >> 3) & 0x70))

__device__ __forceinline__ void split_bf16(float v, uint16_t& hi, uint16_t& lo) {
    uint16_t h = __bfloat16_as_ushort(__float2bfloat16(v));
    float hf = __uint_as_float((uint32_t)h << 16);
    lo = __bfloat16_as_ushort(__float2bfloat16(v - hf));
    hi = h;
}
__device__ __forceinline__ void pack2_bf16(float a, float b,
                                           uint32_t& hi, uint32_t& lo) {
    uint16_t h0, l0, h1, l1;
    split_bf16(a, h0, l0);
    split_bf16(b, h1, l1);
    hi = (uint32_t)h0 | ((uint32_t)h1 << 16);
    lo = (uint32_t)l0 | ((uint32_t)l1 << 16);
}

#if HAS_TC
__device__ __forceinline__ uint32_t elect_one_pred() {
    uint32_t pred;
    asm volatile("{\n\t.reg .pred p;\n\telect.sync _|p, 0xFFFFFFFF;\n\t"
                 "selp.b32 %0, 1, 0, p;\n\t}" : "=r"(pred));
    return pred;
}
__device__ __forceinline__ uint32_t smem_to_u32(const void* p) {
    uint32_t a;
    asm("{ .reg .u64 t; cvta.to.shared.u64 t, %1; cvt.u32.u64 %0, t; }"
        : "=r"(a) : "l"(p));
    return a;
}

static constexpr uint64_t SMEM_DESC_BASE_SW128 =
    (uint64_t(2)  << 61) | (uint64_t(1) << 46) | (uint64_t(64) << 32) | (uint64_t(1) << 16);
#define MAKE_SMEM_DESC(base_addr) \
    (SMEM_DESC_BASE_SW128 | ((uint64_t)((base_addr) >> 4) & 0x3FFF))

#define TCGEN05_ALLOC(smem_result_addr, nCols) \
    asm volatile("tcgen05.alloc.cta_group::1.sync.aligned.shared::cta.b32 [%0], %1;" \
        :: "r"((uint32_t)(smem_result_addr)), "r"((uint32_t)(nCols)) : "memory")
#define TCGEN05_RELINQUISH() \
    asm volatile("tcgen05.relinquish_alloc_permit.cta_group::1.sync.aligned;")
#define TCGEN05_DEALLOC(tmem_addr, nCols) \
    asm volatile("tcgen05.dealloc.cta_group::1.sync.aligned.b32 %0, %1;" \
        :: "r"(tmem_addr), "r"((uint32_t)(nCols)))
#define TCGEN05_COMMIT(mbar) \
    asm volatile("tcgen05.commit.cta_group::1.mbarrier::arrive::one.shared::cluster.b64 [%0];" \
        :: "r"((uint32_t)(mbar)) : "memory")
#define TCGEN05_FENCE_AFTER() \
    asm volatile("tcgen05.fence::after_thread_sync;" ::: "memory")
#define TCGEN05_FENCE_BEFORE() \
    asm volatile("tcgen05.fence::before_thread_sync;" ::: "memory")
#define TCGEN05_WAIT_LD() \
    asm volatile("tcgen05.wait::ld.sync.aligned;" ::: "memory")
#define TCGEN05_WAIT_ST() \
    asm volatile("tcgen05.wait::st.sync.aligned;" ::: "memory")

#define MBARRIER_INIT(mbar, count) \
    asm volatile("mbarrier.init.shared.b64 [%0], %1;" \
        :: "r"((uint32_t)(mbar)), "r"((uint32_t)(count)) : "memory")
#define MBARRIER_WAIT_PARITY(mbar_smem_addr, phase_parity) do { \
    uint32_t _mbar = (uint32_t)(mbar_smem_addr); \
    uint32_t _parity = (uint32_t)(phase_parity); \
    uint32_t _done; \
    asm volatile("{\n\t.reg .pred p;\n\t" \
        "mbarrier.try_wait.parity.acquire.cta.shared::cta.b64 p, [%1], %2;\n\t" \
        "selp.b32 %0, 1, 0, p;\n\t}" \
        : "=r"(_done) : "r"(_mbar), "r"(_parity) : "memory"); \
    if (!_done) { \
        asm volatile("{\n\t.reg .pred P1;\n\t" \
            "WAIT_LOOP_%=:\n\t" \
            "mbarrier.try_wait.parity.acquire.cta.shared::cta.b64 P1, [%0], %1, 0x989680;\n\t" \
            "@P1 bra.uni WAIT_DONE_%=;\n\t" \
            "bra.uni WAIT_LOOP_%=;\n\t" \
            "WAIT_DONE_%=:\n\t}" \
            :: "r"(_mbar), "r"(_parity) : "memory"); \
    } \
} while(0)

#define TCGEN05_LD_32X32B_X32(r, tmem_addr) \
    asm volatile("tcgen05.ld.sync.aligned.32x32b.x32.b32 " \
        "{%0, %1, %2, %3, %4, %5, %6, %7, %8, %9, %10, %11, %12, %13, %14, %15, " \
        " %16, %17, %18, %19, %20, %21, %22, %23, %24, %25, %26, %27, %28, %29, %30, %31}, [%32];" \
        : "=r"((r)[0]),  "=r"((r)[1]),  "=r"((r)[2]),  "=r"((r)[3]), \
          "=r"((r)[4]),  "=r"((r)[5]),  "=r"((r)[6]),  "=r"((r)[7]), \
          "=r"((r)[8]),  "=r"((r)[9]),  "=r"((r)[10]), "=r"((r)[11]), \
          "=r"((r)[12]), "=r"((r)[13]), "=r"((r)[14]), "=r"((r)[15]), \
          "=r"((r)[16]), "=r"((r)[17]), "=r"((r)[18]), "=r"((r)[19]), \
          "=r"((r)[20]), "=r"((r)[21]), "=r"((r)[22]), "=r"((r)[23]), \
          "=r"((r)[24]), "=r"((r)[25]), "=r"((r)[26]), "=r"((r)[27]), \
          "=r"((r)[28]), "=r"((r)[29]), "=r"((r)[30]), "=r"((r)[31]) \
        : "r"(tmem_addr))

#define TCGEN05_ST_32X32B_X32(tmem_addr, r) \
    asm volatile("tcgen05.st.sync.aligned.32x32b.x32.b32 [%0], " \
        "{%1, %2, %3, %4, %5, %6, %7, %8, %9, %10, %11, %12, %13, %14, %15, %16, " \
        " %17, %18, %19, %20, %21, %22, %23, %24, %25, %26, %27, %28, %29, %30, %31, %32};" \
        :: "r"(tmem_addr), \
           "r"((r)[0]),  "r"((r)[1]),  "r"((r)[2]),  "r"((r)[3]), \
           "r"((r)[4]),  "r"((r)[5]),  "r"((r)[6]),  "r"((r)[7]), \
           "r"((r)[8]),  "r"((r)[9]),  "r"((r)[10]), "r"((r)[11]), \
           "r"((r)[12]), "r"((r)[13]), "r"((r)[14]), "r"((r)[15]), \
           "r"((r)[16]), "r"((r)[17]), "r"((r)[18]), "r"((r)[19]), \
           "r"((r)[20]), "r"((r)[21]), "r"((r)[22]), "r"((r)[23]), \
           "r"((r)[24]), "r"((r)[25]), "r"((r)[26]), "r"((r)[27]), \
           "r"((r)[28]), "r"((r)[29]), "r"((r)[30]), "r"((r)[31]) \
        : "memory")

// TS-form bf16 MMA — verified working (R7).
#define TCGEN05_MMA_F16_TS(d_tmem, a_tmem, b_desc, idesc, enable_d) do { \
    uint32_t _enable = (enable_d) ? 1 : 0; \
    uint32_t _zero = 0; \
    asm volatile( \
        "{\n\t" \
        ".reg .pred p;\n\t" \
        "setp.ne.u32 p, %6, 0;\n\t" \
        "tcgen05.mma.cta_group::1.kind::f16 [%0], [%1], %2, %3, " \
        "{%4, %4, %4, %4}, p;\n\t" \
        "}" \
        :: "r"(d_tmem), "r"(a_tmem), "l"(b_desc), "r"(idesc), \
           "r"(_zero), "r"(_zero), "r"(_enable) \
        : "memory"); \
} while(0)

#define BF16_IDESC_N32 0x8080490u
#endif  // HAS_TC

// ---------------------------------------------------------------------------
__global__ void clear_flags_kernel() { g_flags[0] = 0; g_flags[1] = 0; }

// ---------------------------------------------------------------------------
// tcgen05 GEMM — R7's verified SYNCHRONOUS flow + alloc-permit relinquish +
// R9's loader-packed A conversion (both individually verified correct).
// C tile 128x128, K=1024 in 16 chunks of 64. D = Ah*Bh + Ah*Bl + Al*Bh.
// TMEM: alloc 256; D @0..127, Ah @128..159, Al @160..191 (fixed slots).
// SMEM: hdr 1KB (tmem ptr @0, mbar @16);
//   Ahs @1024  u32[128][33] packed A-hi (stride 33 -> conflict-free reads)
//   Als @18432 u32[128][33] packed A-lo
//   Bh  @35840 4 x 4KB SW128 N=32 subtiles;  Bl @52224.  Total 68608.
// ---------------------------------------------------------------------------
#define TC_SMEM 68608

__global__ __launch_bounds__(256) void tc_gemm_kernel(
    const float* __restrict__ A, const float* __restrict__ W,
    const float* __restrict__ bias, float* __restrict__ C,
    int N_total, int bn_base, int scatter)
{
    extern __shared__ char smem[];
    int tid = threadIdx.x;
    int bm = blockIdx.y * 128;
    int bn = bn_base + blockIdx.x * 128;

#if HAS_TC
    uint32_t sb = smem_to_u32(smem);
    int wid = tid >> 5, lid = tid & 31;

    if (wid == 0) {
        TCGEN05_ALLOC(sb, 256);
        TCGEN05_RELINQUISH();        // release SM alloc permit for co-resident CTAs
    }
    if (tid == 0) MBARRIER_INIT(sb + 16, 1);
    __syncthreads();
    uint32_t tmem;
    asm volatile("ld.shared.b32 %0, [%1];" : "=r"(tmem) : "r"(sb));

    uint32_t* const Ahs = (uint32_t*)(smem + 1024);
    uint32_t* const Als = (uint32_t*)(smem + 18432);
    const uint32_t oBh = 35840, oBl = 52224;
    char* const pBh = smem + oBh;
    char* const pBl = smem + oBl;

    for (int c = 0; c < 16; c++) {              // K chunks of 64
        int k0 = c * 64;

        // ---- coalesced fp32 loads (R7 indexing: half-warp per row) ----
        float4 av[8], bv[8];
#pragma unroll
        for (int i = 0; i < 8; i++) {
            int e  = tid + 256 * i;             // 0..2047
            int r  = e >> 4, c4 = e & 15;       // A: row r, float4 col c4
            av[i] = *(const float4*)&A[(size_t)(bm + r) * 1024 + k0 + c4 * 4];
            int kk = e >> 5, ng = e & 31;       // B: k-row kk, n-group ng
            bv[i] = *(const float4*)&W[(size_t)(k0 + kk) * N_total + bn + ng * 4];
        }

        // ---- split once in loader: A packed stride-33, B SW128 subtiles ----
#pragma unroll
        for (int i = 0; i < 8; i++) {
            int e = tid + 256 * i;
            {
                int r = e >> 4, c4 = e & 15;
                uint32_t h0, l0, h1, l1;
                pack2_bf16(av[i].x, av[i].y, h0, l0);
                pack2_bf16(av[i].z, av[i].w, h1, l1);
                int base = r * 33 + c4 * 2;
                Ahs[base] = h0;  Ahs[base + 1] = h1;
                Als[base] = l0;  Als[base + 1] = l1;
            }
            {
                int kk = e >> 5, ng = e & 31;
                float vals[4] = { bv[i].x, bv[i].y, bv[i].z, bv[i].w };
#pragma unroll
                for (int t = 0; t < 4; t++) {
                    int n  = ng * 4 + t;
                    int nt = n >> 5, nr = n & 31;
                    uint16_t h, l;
                    split_bf16(vals[t], h, l);
                    uint32_t o2 = nt * 4096 + SMEM_SWIZZLE_128B((uint32_t)(nr * 128 + kk * 2));
                    *(uint16_t*)(pBh + o2) = h;
                    *(uint16_t*)(pBl + o2) = l;
                }
            }
        }
        __syncthreads();

        // ---- A -> TMEM (warpgroup 0, one row/thread; R9-verified) ----
        if (tid < 128) {
            uint32_t hi[32], lo[32];
            const uint32_t* bh = &Ahs[tid * 33];
            const uint32_t* bl = &Als[tid * 33];
#pragma unroll
            for (int j = 0; j < 32; j++) { hi[j] = bh[j]; lo[j] = bl[j]; }
            uint32_t wofs = ((uint32_t)(tid >> 5)) << 21;
            TCGEN05_ST_32X32B_X32(tmem + 128 + wofs, hi);
            TCGEN05_ST_32X32B_X32(tmem + 160 + wofs, lo);
            TCGEN05_WAIT_ST();
        }
        __syncthreads();

        // ---- MMA (warp 0, elected); all threads wait on commit (R7 flow) ----
        if (wid == 0) {
            uint64_t dbh = MAKE_SMEM_DESC(sb + oBh);
            uint64_t dbl = MAKE_SMEM_DESC(sb + oBl);
            if (elect_one_pred()) {
#pragma unroll
                for (int ks = 0; ks < 4; ks++) {
                    uint32_t ah = tmem + 128 + ks * 8;
                    uint32_t al = tmem + 160 + ks * 8;
#pragma unroll
                    for (int nt = 0; nt < 4; nt++) {
                        uint32_t d  = tmem + nt * 32;
                        uint64_t bo = (uint64_t)(nt * 256) + ks * 2;
                        uint32_t en0 = (c > 0 || ks > 0) ? 1u : 0u;
                        TCGEN05_MMA_F16_TS(d, ah, dbh + bo, BF16_IDESC_N32, en0);
                        TCGEN05_MMA_F16_TS(d, ah, dbl + bo, BF16_IDESC_N32, 1u);
                        TCGEN05_MMA_F16_TS(d, al, dbh + bo, BF16_IDESC_N32, 1u);
                    }
                }
                TCGEN05_COMMIT(sb + 16);
            }
        }
        MBARRIER_WAIT_PARITY(sb + 16, c & 1);
        TCGEN05_FENCE_AFTER();
        __syncthreads();
    }

    // Epilogue (R7-verified): warps 0-3 read D in 32-col rounds
    if (wid < 4) {
        int m = bm + wid * 32 + lid;
        int b = m >> 12, t = m & 4095;
#pragma unroll
        for (int g = 0; g < 4; g++) {
            uint32_t r[32];
            TCGEN05_LD_32X32B_X32(r, tmem + g * 32);
            TCGEN05_WAIT_LD();
            int ncol0 = bn + g * 32;
            if (scatter) {
                int which = ncol0 >> 10;               // 1 = k, 2 = v
                float* dst = (which == 1) ? g_k : g_v;
#pragma unroll
                for (int jj = 0; jj < 32; jj += 4) {
                    int n0 = ncol0 + jj;
                    int h = (n0 & 1023) >> 6, j0 = n0 & 63;
                    float* p = dst + (((size_t)(b * Hn + h) * Tn) + t) * HD + j0;
                    float4 v;
                    v.x = __uint_as_float(r[jj + 0]) + bias[n0 + 0];
                    v.y = __uint_as_float(r[jj + 1]) + bias[n0 + 1];
                    v.z = __uint_as_float(r[jj + 2]) + bias[n0 + 2];
                    v.w = __uint_as_float(r[jj + 3]) + bias[n0 + 3];
                    *(float4*)p = v;
                }
            } else {
                float* p = C + (size_t)m * 1024 + ncol0;
#pragma unroll
                for (int jj = 0; jj < 32; jj += 4) {
                    float4 v;
                    v.x = __uint_as_float(r[jj + 0]) + bias[ncol0 + jj + 0];
                    v.y = __uint_as_float(r[jj + 1]) + bias[ncol0 + jj + 1];
                    v.z = __uint_as_float(r[jj + 2]) + bias[ncol0 + jj + 2];
                    v.w = __uint_as_float(r[jj + 3]) + bias[ncol0 + jj + 3];
                    *(float4*)&p[jj] = v;
                }
            }
        }
        TCGEN05_FENCE_BEFORE();
    }
    __syncthreads();
    if (wid == 0) TCGEN05_DEALLOC(tmem, 256);
#else
    // Non-arch-specific pass: never executed (driver loads sm_103a cubin).
    // If it somehow ran, checks flag -> guard kernels recompute in FFMA.
    (void)A; (void)W; (void)bias; (void)C; (void)N_total;
#endif
}

// ---------------------------------------------------------------------------
// Check kernels: 1 warp per 128x128 output tile verifies 32 elements.
// ---------------------------------------------------------------------------
__global__ __launch_bounds__(256) void check_kv_kernel(
    const float* __restrict__ x, const float* __restrict__ W,
    const float* __restrict__ bias)
{
    int w = (blockIdx.x * blockDim.x + threadIdx.x) >> 5;
    int lane = threadIdx.x & 31;
    if (w >= 128 * 16) return;
    int ty = w >> 4, tx = w & 15;
    int m  = ty * 128 + ((ty * 7 + tx * 3) & 127);
    int n0 = 1024 + tx * 128 + ((ty * 29 + tx * 13) & 96);
    int n  = n0 + lane;
    float acc = bias[n];
    const float* xr = &x[(size_t)m * 1024];
    for (int k = 0; k < 1024; k++)
        acc += xr[k] * W[(size_t)k * 3072 + n];
    int which = n >> 10;
    const float* dst = (which == 1) ? g_k : g_v;
    int h = (n & 1023) >> 6, j0 = n & 63, b = m >> 12, t = m & 4095;
    float got = dst[(((size_t)(b * Hn + h) * Tn) + t) * HD + j0];
    float diff = fabsf(got - acc);
    if (!(diff <= 3e-3f * (1.0f + fabsf(acc)))) atomicExch(&g_flags[0], 1);
}

__global__ __launch_bounds__(256) void check_proj_kernel(
    const float* __restrict__ W, const float* __restrict__ bias,
    const float* __restrict__ out)
{
    int w = (blockIdx.x * blockDim.x + threadIdx.x) >> 5;
    int lane = threadIdx.x & 31;
    if (w >= 128 * 8) return;
    int ty = w >> 3, tx = w & 7;
    int m  = ty * 128 + ((ty * 7 + tx * 3) & 127);
    int n  = tx * 128 + ((ty * 29 + tx * 13) & 96) + lane;
    float acc = bias[n];
    const float* xr = &g_xo[(size_t)m * 1024];
    for (int k = 0; k < 1024; k++)
        acc += xr[k] * W[(size_t)k * 1024 + n];
    float got = out[(size_t)m * 1024 + n];
    float diff = fabsf(got - acc);
    if (!(diff <= 3e-3f * (1.0f + fabsf(acc)))) atomicExch(&g_flags[1], 1);
}

// ---------------------------------------------------------------------------
// Guarded FFMA GEMMs (run only if the TC result was flagged bad).
// ---------------------------------------------------------------------------
__global__ __launch_bounds__(256) void guard_kv_kernel(
    const float* __restrict__ X, const float* __restrict__ W,
    const float* __restrict__ bias)
{
    if (*(volatile int*)&g_flags[0] == 0) return;
    const int K = Dn, N = 3 * Dn;
    __shared__ float As[8][128];
    __shared__ float Bs[8][128];
    int tid = threadIdx.x;
    int bm = blockIdx.y * 128;
    int bn = 1024 + blockIdx.x * 128;
    int arow = tid >> 1,  acol = (tid & 1) << 2;
    int brow = tid >> 5,  bcol = (tid & 31) << 2;
    const float* Ap = X + (size_t)(bm + arow) * K + acol;
    const float* Bp = W + (size_t)brow * N + bn + bcol;
    int ty = tid >> 4, tx = tid & 15;
    float acc[8][8];
#pragma unroll
    for (int i = 0; i < 8; i++)
#pragma unroll
        for (int j = 0; j < 8; j++) acc[i][j] = 0.f;
    for (int k0 = 0; k0 < K; k0 += 8) {
        float4 a4 = *(const float4*)Ap;
        float4 b4 = *(const float4*)Bp;
        As[acol + 0][arow] = a4.x;
        As[acol + 1][arow] = a4.y;
        As[acol + 2][arow] = a4.z;
        As[acol + 3][arow] = a4.w;
        *(float4*)&Bs[brow][bcol] = b4;
        __syncthreads();
#pragma unroll
        for (int kk = 0; kk < 8; kk++) {
            float a[8], b[8];
            *(float4*)&a[0] = *(const float4*)&As[kk][ty * 8];
            *(float4*)&a[4] = *(const float4*)&As[kk][ty * 8 + 4];
            *(float4*)&b[0] = *(const float4*)&Bs[kk][tx * 8];
            *(float4*)&b[4] = *(const float4*)&Bs[kk][tx * 8 + 4];
#pragma unroll
            for (int i = 0; i < 8; i++)
#pragma unroll
                for (int j = 0; j < 8; j++) acc[i][j] += a[i] * b[j];
        }
        __syncthreads();
        Ap += 8;
        Bp += (size_t)8 * N;
    }
    int n0 = bn + tx * 8;
    int which = n0 >> 10;
    float* dst = (which == 1) ? g_k : g_v;
    int h = (n0 & 1023) >> 6, j0 = n0 & 63;
    float bb[8];
#pragma unroll
    for (int j = 0; j < 8; j++) bb[j] = bias[n0 + j];
#pragma unroll
    for (int i = 0; i < 8; i++) {
        int m = bm + ty * 8 + i;
        int b = m >> 12, t = m & 4095;
        float* row = dst + (((size_t)(b * Hn + h) * Tn) + t) * HD + j0;
#pragma unroll
        for (int j = 0; j < 8; j++) row[j] = acc[i][j] + bb[j];
    }
}

__global__ __launch_bounds__(256) void guard_proj_kernel(
    const float* __restrict__ W, const float* __restrict__ bias,
    float* __restrict__ C)
{
    if (*(volatile int*)&g_flags[1] == 0) return;
    const int K = Dn, N = Dn;
    __shared__ float As[8][128];
    __shared__ float Bs[8][128];
    int tid = threadIdx.x;
    int bm = blockIdx.y * 128;
    int bn = blockIdx.x * 128;
    int arow = tid >> 1,  acol = (tid & 1) << 2;
    int brow = tid >> 5,  bcol = (tid & 31) << 2;
    const float* Ap = g_xo + (size_t)(bm + arow) * K + acol;
    const float* Bp = W + (size_t)brow * N + bn + bcol;
    int ty = tid >> 4, tx = tid & 15;
    float acc[8][8];
#pragma unroll
    for (int i = 0; i < 8; i++)
#pragma unroll
        for (int j = 0; j < 8; j++) acc[i][j] = 0.f;
    for (int k0 = 0; k0 < K; k0 += 8) {
        float4 a4 = *(const float4*)Ap;
        float4 b4 = *(const float4*)Bp;
        As[acol + 0][arow] = a4.x;
        As[acol + 1][arow] = a4.y;
        As[acol + 2][arow] = a4.z;
        As[acol + 3][arow] = a4.w;
        *(float4*)&Bs[brow][bcol] = b4;
        __syncthreads();
#pragma unroll
        for (int kk = 0; kk < 8; kk++) {
            float a[8], b[8];
            *(float4*)&a[0] = *(const float4*)&As[kk][ty * 8];
            *(float4*)&a[4] = *(const float4*)&As[kk][ty * 8 + 4];
            *(float4*)&b[0] = *(const float4*)&Bs[kk][tx * 8];
            *(float4*)&b[4] = *(const float4*)&Bs[kk][tx * 8 + 4];
#pragma unroll
            for (int i = 0; i < 8; i++)
#pragma unroll
                for (int j = 0; j < 8; j++) acc[i][j] += a[i] * b[j];
        }
        __syncthreads();
        Ap += 8;
        Bp += (size_t)8 * N;
    }
    float bb[8];
#pragma unroll
    for (int j = 0; j < 8; j++) bb[j] = bias[bn + tx * 8 + j];
#pragma unroll
    for (int i = 0; i < 8; i++) {
        int m = bm + ty * 8 + i;
        float* row = C + (size_t)m * N + bn + tx * 8;
#pragma unroll
        for (int j = 0; j < 8; j++) row[j] = acc[i][j] + bb[j];
    }
}

// ---------------------------------------------------------------------------
// FFMA GEMM for the Q third (bit-identical to round-0; bucket-stable).
// ---------------------------------------------------------------------------
__global__ __launch_bounds__(256) void gemm_qkv_kernel(
    const float* __restrict__ X, const float* __restrict__ W,
    const float* __restrict__ bias)
{
    const int K = Dn, N = 3 * Dn;
    __shared__ float As[8][128];
    __shared__ float Bs[8][128];
    int tid = threadIdx.x;
    int bm = blockIdx.y * 128;
    int bn = blockIdx.x * 128;
    int arow = tid >> 1,  acol = (tid & 1) << 2;
    int brow = tid >> 5,  bcol = (tid & 31) << 2;
    const float* Ap = X + (size_t)(bm + arow) * K + acol;
    const float* Bp = W + (size_t)brow * N + bn + bcol;
    int ty = tid >> 4, tx = tid & 15;

    float acc[8][8];
#pragma unroll
    for (int i = 0; i < 8; i++)
#pragma unroll
        for (int j = 0; j < 8; j++) acc[i][j] = 0.f;

    for (int k0 = 0; k0 < K; k0 += 8) {
        float4 a4 = *(const float4*)Ap;
        float4 b4 = *(const float4*)Bp;
        As[acol + 0][arow] = a4.x;
        As[acol + 1][arow] = a4.y;
        As[acol + 2][arow] = a4.z;
        As[acol + 3][arow] = a4.w;
        *(float4*)&Bs[brow][bcol] = b4;
        __syncthreads();
#pragma unroll
        for (int kk = 0; kk < 8; kk++) {
            float a[8], b[8];
            *(float4*)&a[0] = *(const float4*)&As[kk][ty * 8];
            *(float4*)&a[4] = *(const float4*)&As[kk][ty * 8 + 4];
            *(float4*)&b[0] = *(const float4*)&Bs[kk][tx * 8];
            *(float4*)&b[4] = *(const float4*)&Bs[kk][tx * 8 + 4];
#pragma unroll
            for (int i = 0; i < 8; i++)
#pragma unroll
                for (int j = 0; j < 8; j++) acc[i][j] += a[i] * b[j];
        }
        __syncthreads();
        Ap += 8;
        Bp += (size_t)8 * N;
    }

    int n0 = bn + tx * 8;
    int h  = (n0 & 1023) >> 6;
    int j0 = n0 & 63;
    float bb[8];
#pragma unroll
    for (int j = 0; j < 8; j++) bb[j] = bias[n0 + j];
#pragma unroll
    for (int i = 0; i < 8; i++) {
        int m = bm + ty * 8 + i;
        int b = m >> 12;
        int t = m & 4095;
        float* row = g_q + (((size_t)(b * Hn + h) * Tn) + t) * HD + j0;
#pragma unroll
        for (int j = 0; j < 8; j++) row[j] = acc[i][j] + bb[j];
    }
}

// ---------------------------------------------------------------------------
__global__ void rope_kernel()
{
    int idx = blockIdx.x * blockDim.x + threadIdx.x;
    if (idx >= BH * Tn * 32) return;
    int p  = idx & 31;
    int rt = idx >> 5;
    int t  = rt & 4095;
    int d0 = p * 2, d1 = p * 2 + 1;
    float e0 = (float)(d0 & 31) * (1.0f / 32.0f);
    float e1 = (float)(d1 & 31) * (1.0f / 32.0f);
    float inv0 = 1.0f / powf(10000.0f, e0);
    float inv1 = 1.0f / powf(10000.0f, e1);
    float a0 = (float)t * inv0, a1 = (float)t * inv1;
    float s0, c0, s1, c1;
    sincosf(a0, &s0, &c0);
    sincosf(a1, &s1, &c1);
    size_t base = (size_t)rt * HD;
    float q0 = g_q[base + d0], q1 = g_q[base + d1];
    g_q[base + d0] = q0 * c0 - q1 * s0;
    g_q[base + d1] = q1 * c1 + q0 * s1;
    float k0 = g_k[base + d0], k1 = g_k[base + d1];
    g_k[base + d0] = k0 * c0 - k1 * s0;
    g_k[base + d1] = k1 * c1 + k0 * s1;
}

// ---------------------------------------------------------------------------
__global__ __launch_bounds__(128) void bucket_kernel(const float* __restrict__ R)
{
    __shared__ float Rs[64 * 32];
    int tid = threadIdx.x;
    for (int i = tid; i < 2048; i += 128) {
        int d = i >> 5, m = i & 31;
        Rs[i] = R[d * 64 + m];
    }
    __syncthreads();

    int idx = blockIdx.x * 128 + tid;
    float q[64];
    const float* qp = &g_q[(size_t)idx * HD];
#pragma unroll
    for (int l = 0; l < 16; l++) *(float4*)&q[l * 4] = *(const float4*)&qp[l * 4];

    float proj[32];
    for (int m = 0; m < 32; m++) {
        float s = 0.f;
#pragma unroll
        for (int d = 0; d < 64; d++) s += q[d] * Rs[d * 32 + m];
        proj[m] = s;
    }
    float best = -1e30f; int bi = 0;
#pragma unroll
    for (int i = 0; i < 64; i++) {
        float v = (i < 32) ? proj[i] : -proj[i - 32];
        if (v > best) { best = v; bi = i; }
    }
    g_keys[idx] = ((unsigned)bi << 12) | (unsigned)(idx & 4095);
}

// ---------------------------------------------------------------------------
__global__ __launch_bounds__(1024) void sort_kernel()
{
    __shared__ unsigned s[4096];
    int bh = blockIdx.x, tid = threadIdx.x;
    for (int i = tid; i < 4096; i += 1024) s[i] = g_keys[bh * 4096 + i];
    __syncthreads();
    for (int k = 2; k <= 4096; k <<= 1) {
        for (int j = k >> 1; j > 0; j >>= 1) {
            for (int i = tid; i < 4096; i += 1024) {
                int ixj = i ^ j;
                if (ixj > i) {
                    unsigned a = s[i], b = s[ixj];
                    bool up = (i & k) == 0;
                    if ((a > b) == up) { s[i] = b; s[ixj] = a; }
                }
            }
            __syncthreads();
        }
    }
    for (int i = tid; i < 4096; i += 1024)
        g_sidx[bh * 4096 + i] = (int)(s[i] & 4095u);
}

// ---------------------------------------------------------------------------
#define ATTN_SMEM ((8192 + 8192 + 128 * 129) * 4)

__global__ __launch_bounds__(128) void attn_kernel()
{
    extern __shared__ float sm[];
    float* Ks = sm;
    float* Vs = sm + 8192;
    float* Ss = sm + 16384;
    __shared__ int sidx_s[128];

    int bc = blockIdx.x;
    int bh = bc >> 5;
    int c  = bc & 31;
    int p0 = c * 128;
    int tid = threadIdx.x;
    const int rowbase = bh * Tn;

    sidx_s[tid] = g_sidx[rowbase + p0 + tid];
    __syncthreads();

    for (int i = tid; i < 128 * 16; i += 128) {
        int r = i >> 4, l = (i & 15) * 4;
        size_t src = ((size_t)(rowbase + sidx_s[r])) * HD + l;
        *(float4*)&Ks[r * 64 + l] = *(const float4*)&g_k[src];
        *(float4*)&Vs[r * 64 + l] = *(const float4*)&g_v[src];
    }
    __syncthreads();

    int r  = tid;
    int si = sidx_s[r];
    float qr[64];
    {
        const float* qp = &g_q[((size_t)(rowbase + si)) * HD];
#pragma unroll
        for (int l = 0; l < 16; l++) *(float4*)&qr[l * 4] = *(const float4*)&qp[l * 4];
    }

    float mx = -1e30f;
    for (int j = 0; j < 128; j++) {
        const float* kp = &Ks[j * 64];
        float s0 = 0.f, s1 = 0.f, s2 = 0.f, s3 = 0.f;
#pragma unroll
        for (int d = 0; d < 64; d += 4) {
            float4 k4 = *(const float4*)&kp[d];
            s0 += qr[d + 0] * k4.x;
            s1 += qr[d + 1] * k4.y;
            s2 += qr[d + 2] * k4.z;
            s3 += qr[d + 3] * k4.w;
        }
        float s = (s0 + s1 + s2 + s3) * 0.125f;
        Ss[r * 129 + j] = s;
        mx = fmaxf(mx, s);
    }

    float sum = 0.f;
#pragma unroll 4
    for (int j = 0; j < 128; j++) {
        float e = __expf(Ss[r * 129 + j] - mx);
        Ss[r * 129 + j] = e;
        sum += e;
    }
    float inv = 1.0f / sum;

    float o[64];
#pragma unroll
    for (int d = 0; d < 64; d++) o[d] = 0.f;
    for (int j = 0; j < 128; j++) {
        float p = Ss[r * 129 + j];
        const float* vp = &Vs[j * 64];
#pragma unroll
        for (int d = 0; d < 64; d += 4) {
            float4 v4 = *(const float4*)&vp[d];
            o[d + 0] += p * v4.x;
            o[d + 1] += p * v4.y;
            o[d + 2] += p * v4.z;
            o[d + 3] += p * v4.w;
        }
    }

    int b = bh >> 4, h = bh & 15;
    float* op = &g_xo[((size_t)(b * Tn + si)) * Dn + h * HD];
#pragma unroll
    for (int l = 0; l < 16; l++) {
        float4 v4 = make_float4(o[l * 4 + 0] * inv, o[l * 4 + 1] * inv,
                                o[l * 4 + 2] * inv, o[l * 4 + 3] * inv);
        *(float4*)&op[l * 4] = v4;
    }
}

// ---------------------------------------------------------------------------
extern "C" void kernel_launch(void* const* d_in, const int* in_sizes, int n_in,
                              void* d_out, int out_size)
{
    const float* x      = (const float*)d_in[0];
    const float* W_attn = (const float*)d_in[1];
    const float* b_attn = (const float*)d_in[2];
    const float* W_proj = (const float*)d_in[3];
    const float* b_proj = (const float*)d_in[4];
    const float* R      = (const float*)d_in[5];
    float* out = (float*)d_out;

    cudaFuncSetAttribute(attn_kernel,
                         cudaFuncAttributeMaxDynamicSharedMemorySize, ATTN_SMEM);
    cudaFuncSetAttribute(tc_gemm_kernel,
                         cudaFuncAttributeMaxDynamicSharedMemorySize, TC_SMEM);

    clear_flags_kernel<<<1, 1>>>();

    // Q third: exact fp32 FFMA (bucket-stable)
    dim3 gq(8, Mn / 128);
    gemm_qkv_kernel<<<gq, 256>>>(x, W_attn, b_attn);

    // K,V thirds: tcgen05 (R7 flow + relinquish + loader-packed A)
    dim3 gkv(16, Mn / 128);
    tc_gemm_kernel<<<gkv, 256, TC_SMEM>>>(x, W_attn, b_attn, g_xo,
                                          3 * Dn, 1024, 1);
    check_kv_kernel<<<(128 * 16 * 32 + 255) / 256, 256>>>(x, W_attn, b_attn);
    guard_kv_kernel<<<gkv, 256>>>(x, W_attn, b_attn);

    rope_kernel<<<(BH * Tn * 32 + 255) / 256, 256>>>();
    bucket_kernel<<<BH * Tn / 128, 128>>>(R);
    sort_kernel<<<BH, 1024>>>();
    attn_kernel<<<BH * NCH, 128, ATTN_SMEM>>>();

    // Output projection: tcgen05 + verify + fallback
    dim3 go(8, Mn / 128);
    tc_gemm_kernel<<<go, 256, TC_SMEM>>>(g_xo, W_proj, b_proj, out,
                                         Dn, 0, 0);
    check_proj_kernel<<<(128 * 8 * 32 + 255) / 256, 256>>>(W_proj, b_proj, out);
    guard_proj_kernel<<<go, 256>>>(W_proj, b_proj, out);
}